// round 7
// baseline (speedup 1.0000x reference)
#include <cuda_runtime.h>
#include <cuda_fp16.h>
#include <cstdint>

#define BB 4
#define TT 2048
#define SS 2048
#define CC 1024
#define HH 16
#define DD 64
#define SCALE_F 0.125f
#define MT (BB * TT)

typedef unsigned long long u64;
typedef unsigned int u32;
typedef unsigned short u16;

// ---------------------------------------------------------------------------
// Scratch (allocation-free rule: __device__ globals)
// ---------------------------------------------------------------------------
__device__ u16 g_xh[3][MT * CC];          // input splits (q,k,v) bf16 hi
__device__ u16 g_xl[3][MT * CC];          // bf16 lo
__device__ u16 g_wh[4][CC * CC];          // weight splits (q,k,v,out) bf16 hi
__device__ u16 g_wl[4][CC * CC];
__device__ u16 g_ph[3][BB * HH * TT * DD]; // projected q,k,v f16 hi (B,H,T,D)
__device__ u16 g_pl[3][BB * HH * TT * DD]; // f16 lo
__device__ u16 g_ah[MT * CC];             // attn out bf16 hi (B,T,C)
__device__ u16 g_al[MT * CC];
__device__ int g_flags;                   // bit0: mask nonzero, bit1: kpm any

// ---------------------------------------------------------------------------
// helpers
// ---------------------------------------------------------------------------
__device__ __forceinline__ u32 smem_u32(const void* p) {
    u32 a;
    asm("{ .reg .u64 t; cvta.to.shared.u64 t, %1; cvt.u32.u64 %0, t; }" : "=r"(a) : "l"(p));
    return a;
}
__device__ __forceinline__ void ldsm4(u32 addr, u32& r0, u32& r1, u32& r2, u32& r3) {
    asm volatile("ldmatrix.sync.aligned.m8n8.x4.shared.b16 {%0,%1,%2,%3},[%4];"
                 : "=r"(r0), "=r"(r1), "=r"(r2), "=r"(r3) : "r"(addr));
}
__device__ __forceinline__ void ldsm4t(u32 addr, u32& r0, u32& r1, u32& r2, u32& r3) {
    asm volatile("ldmatrix.sync.aligned.m8n8.x4.trans.shared.b16 {%0,%1,%2,%3},[%4];"
                 : "=r"(r0), "=r"(r1), "=r"(r2), "=r"(r3) : "r"(addr));
}
__device__ __forceinline__ void mma_bf(float* c, const u32* a, const u32* b) {
    asm volatile(
        "mma.sync.aligned.m16n8k16.row.col.f32.bf16.bf16.f32 "
        "{%0,%1,%2,%3},{%4,%5,%6,%7},{%8,%9},{%0,%1,%2,%3};"
        : "+f"(c[0]), "+f"(c[1]), "+f"(c[2]), "+f"(c[3])
        : "r"(a[0]), "r"(a[1]), "r"(a[2]), "r"(a[3]), "r"(b[0]), "r"(b[1]));
}
__device__ __forceinline__ void mma_f16(float* c, const u32* a, const u32* b) {
    asm volatile(
        "mma.sync.aligned.m16n8k16.row.col.f32.f16.f16.f32 "
        "{%0,%1,%2,%3},{%4,%5,%6,%7},{%8,%9},{%0,%1,%2,%3};"
        : "+f"(c[0]), "+f"(c[1]), "+f"(c[2]), "+f"(c[3])
        : "r"(a[0]), "r"(a[1]), "r"(a[2]), "r"(a[3]), "r"(b[0]), "r"(b[1]));
}
__device__ __forceinline__ u32 f16pair(float lo, float hi) {
    u32 r; asm("cvt.rn.f16x2.f32 %0,%1,%2;" : "=r"(r) : "f"(hi), "f"(lo)); return r;
}
__device__ __forceinline__ void h2unpack(u32 v, float& lo, float& hi) {
    asm("{.reg .b16 l,h; mov.b32 {l,h}, %2; cvt.f32.f16 %0, l; cvt.f32.f16 %1, h;}"
        : "=f"(lo), "=f"(hi) : "r"(v));
}
__device__ __forceinline__ void cpa16(u32 dst, const void* src) {
    asm volatile("cp.async.cg.shared.global [%0], [%1], 16;" :: "r"(dst), "l"(src));
}
__device__ __forceinline__ void cpa_commit() {
    asm volatile("cp.async.commit_group;" ::: "memory");
}
__device__ __forceinline__ void cpa_wait0() {
    asm volatile("cp.async.wait_group 0;" ::: "memory");
}
// bf16 split: hi = truncation (exact), lo = rn(x - hi)
__device__ __forceinline__ void split2_bf16(float x, float y, u32& hi, u32& lo) {
    u32 ax = __float_as_uint(x), ay = __float_as_uint(y);
    asm("prmt.b32 %0,%1,%2,0x7632;" : "=r"(hi) : "r"(ax), "r"(ay));
    float rx = x - __uint_as_float(ax & 0xffff0000u);
    float ry = y - __uint_as_float(ay & 0xffff0000u);
    asm("cvt.rn.bf16x2.f32 %0,%1,%2;" : "=r"(lo) : "f"(ry), "f"(rx));
}
// f16 split: hi = rn f16, lo = rn f16 of residual
__device__ __forceinline__ void split2_f16(float x, float y, u32& hi, u32& lo) {
    hi = f16pair(x, y);
    float hx, hy; h2unpack(hi, hx, hy);
    lo = f16pair(x - hx, y - hy);
}

// ---------------------------------------------------------------------------
// pre-split fp32 -> bf16 hi/lo (elementwise, memory-bound)
// ---------------------------------------------------------------------------
__global__ void split_bf16(const float4* __restrict__ in, uint4* __restrict__ hi,
                           uint4* __restrict__ lo, int n8)
{
    int idx = blockIdx.x * blockDim.x + threadIdx.x;
    int stride = gridDim.x * blockDim.x;
    for (int i = idx; i < n8; i += stride) {
        float4 a = __ldg(in + 2 * i), b = __ldg(in + 2 * i + 1);
        uint4 h, l;
        split2_bf16(a.x, a.y, h.x, l.x);
        split2_bf16(a.z, a.w, h.y, l.y);
        split2_bf16(b.x, b.y, h.z, l.z);
        split2_bf16(b.z, b.w, h.w, l.w);
        hi[i] = h; lo[i] = l;
    }
}

// ---------------------------------------------------------------------------
// Mask content check
// ---------------------------------------------------------------------------
__global__ void mask_check(const float* __restrict__ mask,
                           const unsigned char* __restrict__ kpm)
{
    int idx = blockIdx.x * blockDim.x + threadIdx.x;
    int stride = gridDim.x * blockDim.x;
    int any_m = 0;
    const float4* m4 = (const float4*)mask;
    for (int i = idx; i < (TT * SS) / 4; i += stride) {
        float4 v = __ldg(m4 + i);
        any_m |= (v.x != 0.f) | (v.y != 0.f) | (v.z != 0.f) | (v.w != 0.f);
    }
    int any_k = 0;
    const uint4* k4 = (const uint4*)kpm;
    for (int i = idx; i < (BB * SS) / 16; i += stride) {
        uint4 v = __ldg(k4 + i);
        any_k |= ((v.x | v.y | v.z | v.w) != 0u);
    }
    if (__any_sync(0xffffffffu, any_m) && (threadIdx.x & 31) == 0) atomicOr(&g_flags, 1);
    if (__any_sync(0xffffffffu, any_k) && (threadIdx.x & 31) == 0) atomicOr(&g_flags, 2);
}

// ---------------------------------------------------------------------------
// cp.async-pipelined bf16x3 GEMM: out = A @ W^T + bias (A,W pre-split bf16).
// K-chunks of 32, double-buffered. MODE 0: fp32 row-major. MODE 1: f16 hi/lo
// split output scattered to (B,H,T,D), scaled.
// smem per buffer: 4 tiles [128 rows x 80B]: Ahi, Alo, Whi, Wlo.
// ---------------------------------------------------------------------------
#define GST 80
#define GTILE (128 * GST)        // 10240
#define GBUF (4 * GTILE)         // 40960
#define GEMM_SMEM (2 * GBUF)     // 81920

template <int MODE>
__global__ __launch_bounds__(256, 2) void tc_gemm2(
    const u16* __restrict__ Ah, const u16* __restrict__ Al,
    const u16* __restrict__ Wh, const u16* __restrict__ Wl,
    const float* __restrict__ bias,
    void* __restrict__ out_a, void* __restrict__ out_b,
    float scale, int M, int N, int K)
{
    extern __shared__ __align__(128) char dsm[];
    const u32 sb = smem_u32(dsm);
    const int tid = threadIdx.x;
    const int lane = tid & 31;
    const int wid = tid >> 5;
    const int wm = wid & 3;
    const int wn = wid >> 2;
    const int bm = blockIdx.y * 128, bn = blockIdx.x * 128;

    const u16* srcs[4] = { Ah + (size_t)bm * K, Al + (size_t)bm * K,
                           Wh + (size_t)bn * K, Wl + (size_t)bn * K };

    const u32 aOff = (u32)((wm * 32 + (lane & 15)) * GST + (lane >> 4) * 16);
    const u32 bRow = (u32)(((lane >> 4) << 3) + (lane & 7));
    const u32 bOff = (u32)((wn * 64 + bRow) * GST + ((lane >> 3) & 1) * 16);

    float acc[2][8][4];
#pragma unroll
    for (int i = 0; i < 2; i++)
#pragma unroll
        for (int j = 0; j < 8; j++)
#pragma unroll
            for (int q = 0; q < 4; q++) acc[i][j][q] = 0.f;

    auto issue = [&](int c, int buf) {
        u32 dbase = sb + buf * GBUF;
#pragma unroll
        for (int t = 0; t < 4; t++) {
            const u16* sp = srcs[t] + c * 32;
#pragma unroll
            for (int i = 0; i < 2; i++) {
                int s = tid + i * 256;
                int r = s >> 2, j = s & 3;
                cpa16(dbase + t * GTILE + r * GST + j * 16, sp + (size_t)r * K + j * 8);
            }
        }
        cpa_commit();
    };

    issue(0, 0);
    const int nch = K / 32;
    int buf = 0;
    for (int c = 0; c < nch; c++) {
        cpa_wait0();
        __syncthreads();
        if (c + 1 < nch) issue(c + 1, buf ^ 1);
        const u32 base = sb + buf * GBUF;
        const u32 aH = base + aOff, aL = aH + GTILE;
        const u32 bH = base + 2 * GTILE + bOff, bL = bH + GTILE;
#pragma unroll
        for (int ks = 0; ks < 2; ks++) {
            u32 ah[2][4], al[2][4];
#pragma unroll
            for (int mf = 0; mf < 2; mf++) {
                ldsm4(aH + mf * 1280 + ks * 32, ah[mf][0], ah[mf][1], ah[mf][2], ah[mf][3]);
                ldsm4(aL + mf * 1280 + ks * 32, al[mf][0], al[mf][1], al[mf][2], al[mf][3]);
            }
#pragma unroll
            for (int ng = 0; ng < 4; ng++) {
                u32 bh[4], bl[4];
                ldsm4(bH + ng * 1280 + ks * 32, bh[0], bh[1], bh[2], bh[3]);
                ldsm4(bL + ng * 1280 + ks * 32, bl[0], bl[1], bl[2], bl[3]);
#pragma unroll
                for (int half = 0; half < 2; half++) {
                    const u32* bhp = &bh[half * 2];
                    const u32* blp = &bl[half * 2];
                    int nf = ng * 2 + half;
#pragma unroll
                    for (int mf = 0; mf < 2; mf++) {
                        mma_bf(acc[mf][nf], ah[mf], bhp);
                        mma_bf(acc[mf][nf], ah[mf], blp);
                        mma_bf(acc[mf][nf], al[mf], bhp);
                    }
                }
            }
        }
        buf ^= 1;
    }

#pragma unroll
    for (int mf = 0; mf < 2; mf++) {
#pragma unroll
        for (int nf = 0; nf < 8; nf++) {
            int m = bm + wm * 32 + mf * 16 + (lane >> 2);
            int n = bn + wn * 64 + nf * 8 + (lane & 3) * 2;
            float b0 = __ldg(bias + n), b1 = __ldg(bias + n + 1);
            if (MODE == 0) {
                float* out = (float*)out_a;
                *(float2*)(out + (size_t)m * N + n) =
                    make_float2(acc[mf][nf][0] + b0, acc[mf][nf][1] + b1);
                *(float2*)(out + (size_t)(m + 8) * N + n) =
                    make_float2(acc[mf][nf][2] + b0, acc[mf][nf][3] + b1);
            } else {
                u32* oh = (u32*)out_a;
                u32* ol = (u32*)out_b;
                int h = n >> 6, d = n & (DD - 1);
                float v0 = (acc[mf][nf][0] + b0) * scale;
                float v1 = (acc[mf][nf][1] + b1) * scale;
                float v2 = (acc[mf][nf][2] + b0) * scale;
                float v3 = (acc[mf][nf][3] + b1) * scale;
                int b_ = m >> 11, t = m & (TT - 1);
                size_t idx0 = ((((size_t)b_ * HH + h) * TT + t) * DD + d) >> 1;
                u32 hi, lo;
                split2_f16(v0, v1, hi, lo);
                oh[idx0] = hi; ol[idx0] = lo;
                int m1 = m + 8;
                int b1_ = m1 >> 11, t1 = m1 & (TT - 1);
                size_t idx1 = ((((size_t)b1_ * HH + h) * TT + t1) * DD + d) >> 1;
                split2_f16(v2, v3, hi, lo);
                oh[idx1] = hi; ol[idx1] = lo;
            }
        }
    }
}

// ---------------------------------------------------------------------------
// Tensor-core flash attention, cp.async-pipelined.
// Q/K/V arrive pre-split f16 hi/lo (Q pre-scaled). P f16-hi (2-MMA PV).
// smem: Qhi[128x144] 0, Qlo 18432; KV buffers at 36864 + buf*36864:
//   Khi +0 (64x144=9216), Klo +9216, Vhi +18432, Vlo +27648.  Total 110592.
// ---------------------------------------------------------------------------
#define AST 144
#define AQLO 18432
#define AKV0 36864
#define AKVB 36864
#define ATTN_SMEM2 110592

__global__ __launch_bounds__(256, 2) void attn_tc2(
    const float* __restrict__ mask, const unsigned char* __restrict__ kpm,
    const u16* __restrict__ qh, const u16* __restrict__ ql,
    const u16* __restrict__ kh, const u16* __restrict__ kl,
    const u16* __restrict__ vh, const u16* __restrict__ vl,
    u16* __restrict__ ah_out, u16* __restrict__ al_out)
{
    extern __shared__ __align__(128) char smr[];
    const u32 sb = smem_u32(smr);

    const int tid = threadIdx.x;
    const int lane = tid & 31;
    const int w = tid >> 5;
    const int tblk = blockIdx.x * 128;
    const int h = blockIdx.y, b = blockIdx.z;
    const float NEGINF = __int_as_float(0xff800000);

    const int flags = g_flags;
    const bool mflag = (flags & 1) != 0;
    const bool kflag = (flags & 2) != 0;

    const size_t baseq = (((size_t)b * HH + h) * TT + tblk) * DD;
    const size_t basekv = ((size_t)b * HH + h) * (size_t)SS * DD;

    // prologue: cp.async Q tiles (group 1)
#pragma unroll
    for (int t = 0; t < 2; t++) {
        const u16* src = (t ? ql : qh) + baseq;
#pragma unroll
        for (int i = 0; i < 4; i++) {
            int s = tid + i * 256;
            int r = s >> 3, j = s & 7;
            cpa16(sb + t * AQLO + r * AST + j * 16, src + (size_t)r * DD + j * 8);
        }
    }
    cpa_commit();

    auto issueKV = [&](int s0, int buf) {
        const u16* srcs[4] = { kh + basekv, kl + basekv, vh + basekv, vl + basekv };
        u32 dbase = sb + AKV0 + buf * AKVB;
#pragma unroll
        for (int t = 0; t < 4; t++) {
#pragma unroll
            for (int i = 0; i < 2; i++) {
                int s = tid + i * 256;
                int r = s >> 3, j = s & 7;
                cpa16(dbase + t * 9216 + r * AST + j * 16,
                      srcs[t] + (size_t)(s0 + r) * DD + j * 8);
            }
        }
        cpa_commit();
    };
    issueKV(0, 0);

    const u32 aQ = sb + (u32)((w * 16 + (lane & 15)) * AST + (lane >> 4) * 16);
    const u32 bKoff = (u32)((((lane >> 4) << 3) + (lane & 7)) * AST + ((lane >> 3) & 1) * 16);
    const u32 bVoff = (u32)((lane & 15) * AST + (lane >> 4) * 16);

    const int row0 = tblk + w * 16 + (lane >> 2);
    const float* mrow0 = mask + (size_t)row0 * SS;
    const float* mrow1 = mrow0 + 8 * (size_t)SS;

    float O[8][4];
#pragma unroll
    for (int i = 0; i < 8; i++)
#pragma unroll
        for (int j = 0; j < 4; j++) O[i][j] = 0.f;
    float l0 = 0.f, l1 = 0.f, m0 = NEGINF, m1 = NEGINF;

    int buf = 0;
    for (int c = 0; c < SS / 64; c++) {
        const int s0 = c * 64;
        cpa_wait0();
        __syncthreads();
        if (c + 1 < SS / 64) issueKV(s0 + 64, buf ^ 1);

        const u32 kvb = sb + AKV0 + buf * AKVB;
        const u32 bK = kvb + bKoff;
        const u32 bV = kvb + 18432 + bVoff;

        // S = Q K^T  (f16 3-term split, scale pre-folded into Q)
        float sacc[8][4];
#pragma unroll
        for (int i = 0; i < 8; i++)
#pragma unroll
            for (int j = 0; j < 4; j++) sacc[i][j] = 0.f;
#pragma unroll
        for (int ks = 0; ks < 4; ks++) {
            u32 ahf[4], alf[4];
            ldsm4(aQ + ks * 32, ahf[0], ahf[1], ahf[2], ahf[3]);
            ldsm4(aQ + AQLO + ks * 32, alf[0], alf[1], alf[2], alf[3]);
#pragma unroll
            for (int sg = 0; sg < 4; sg++) {
                u32 bh[4], bl[4];
                ldsm4(bK + sg * 2304 + ks * 32, bh[0], bh[1], bh[2], bh[3]);
                ldsm4(bK + 9216 + sg * 2304 + ks * 32, bl[0], bl[1], bl[2], bl[3]);
#pragma unroll
                for (int half = 0; half < 2; half++) {
                    float* cc = sacc[sg * 2 + half];
                    mma_f16(cc, ahf, &bh[half * 2]);
                    mma_f16(cc, ahf, &bl[half * 2]);
                    mma_f16(cc, alf, &bh[half * 2]);
                }
            }
        }

        if (kflag) {
#pragma unroll
            for (int nf = 0; nf < 8; nf++) {
                int col = s0 + nf * 8 + (lane & 3) * 2;
                float k0 = kpm[(size_t)b * SS + col] ? NEGINF : 0.f;
                float k1 = kpm[(size_t)b * SS + col + 1] ? NEGINF : 0.f;
                sacc[nf][0] += k0; sacc[nf][1] += k1;
                sacc[nf][2] += k0; sacc[nf][3] += k1;
            }
        }
        if (mflag) {
#pragma unroll
            for (int nf = 0; nf < 8; nf++) {
                int col = s0 + nf * 8 + (lane & 3) * 2;
                float2 mv0 = __ldg((const float2*)(mrow0 + col));
                float2 mv1 = __ldg((const float2*)(mrow1 + col));
                sacc[nf][0] += mv0.x; sacc[nf][1] += mv0.y;
                sacc[nf][2] += mv1.x; sacc[nf][3] += mv1.y;
            }
        }

        float cm0 = NEGINF, cm1 = NEGINF;
#pragma unroll
        for (int nf = 0; nf < 8; nf++) {
            cm0 = fmaxf(cm0, fmaxf(sacc[nf][0], sacc[nf][1]));
            cm1 = fmaxf(cm1, fmaxf(sacc[nf][2], sacc[nf][3]));
        }
        cm0 = fmaxf(cm0, __shfl_xor_sync(0xffffffffu, cm0, 1));
        cm0 = fmaxf(cm0, __shfl_xor_sync(0xffffffffu, cm0, 2));
        cm1 = fmaxf(cm1, __shfl_xor_sync(0xffffffffu, cm1, 1));
        cm1 = fmaxf(cm1, __shfl_xor_sync(0xffffffffu, cm1, 2));

        float mn0 = fmaxf(m0, cm0), mn1 = fmaxf(m1, cm1);
        float c0 = __expf(m0 - mn0), c1 = __expf(m1 - mn1);
        m0 = mn0; m1 = mn1;
        l0 *= c0; l1 *= c1;
#pragma unroll
        for (int nf = 0; nf < 8; nf++) {
            O[nf][0] *= c0; O[nf][1] *= c0;
            O[nf][2] *= c1; O[nf][3] *= c1;
        }

        u32 phi[8][2];
        float rs0 = 0.f, rs1 = 0.f;
#pragma unroll
        for (int nf = 0; nf < 8; nf++) {
            float p0 = __expf(sacc[nf][0] - mn0);
            float p1 = __expf(sacc[nf][1] - mn0);
            float p2 = __expf(sacc[nf][2] - mn1);
            float p3 = __expf(sacc[nf][3] - mn1);
            rs0 += p0 + p1; rs1 += p2 + p3;
            phi[nf][0] = f16pair(p0, p1);
            phi[nf][1] = f16pair(p2, p3);
        }
        rs0 += __shfl_xor_sync(0xffffffffu, rs0, 1);
        rs0 += __shfl_xor_sync(0xffffffffu, rs0, 2);
        rs1 += __shfl_xor_sync(0xffffffffu, rs1, 1);
        rs1 += __shfl_xor_sync(0xffffffffu, rs1, 2);
        l0 += rs0; l1 += rs1;

        // O += P V  (P-hi x (V-hi + V-lo))
#pragma unroll
        for (int ks = 0; ks < 4; ks++) {
            u32 ap[4] = {phi[2 * ks][0], phi[2 * ks][1],
                         phi[2 * ks + 1][0], phi[2 * ks + 1][1]};
#pragma unroll
            for (int dg = 0; dg < 4; dg++) {
                u32 bh[4], bl[4];
                ldsm4t(bV + ks * 2304 + dg * 32, bh[0], bh[1], bh[2], bh[3]);
                ldsm4t(bV + 9216 + ks * 2304 + dg * 32, bl[0], bl[1], bl[2], bl[3]);
                mma_f16(O[dg * 2], ap, &bh[0]);
                mma_f16(O[dg * 2], ap, &bl[0]);
                mma_f16(O[dg * 2 + 1], ap, &bh[2]);
                mma_f16(O[dg * 2 + 1], ap, &bl[2]);
            }
        }
        buf ^= 1;
    }

    // epilogue: normalize and write bf16 hi/lo split to (B,T,C)
    float i0 = __fdividef(1.f, l0), i1 = __fdividef(1.f, l1);
    size_t base0 = ((size_t)b * TT + row0) * CC + h * DD + (lane & 3) * 2;
    size_t base1 = base0 + 8 * (size_t)CC;
    u32* oh = (u32*)ah_out;
    u32* ol = (u32*)al_out;
#pragma unroll
    for (int nf = 0; nf < 8; nf++) {
        u32 hi, lo;
        split2_bf16(O[nf][0] * i0, O[nf][1] * i0, hi, lo);
        oh[(base0 + nf * 8) >> 1] = hi; ol[(base0 + nf * 8) >> 1] = lo;
        split2_bf16(O[nf][2] * i1, O[nf][3] * i1, hi, lo);
        oh[(base1 + nf * 8) >> 1] = hi; ol[(base1 + nf * 8) >> 1] = lo;
    }
}

// ---------------------------------------------------------------------------
// Launch
// ---------------------------------------------------------------------------
extern "C" void kernel_launch(void* const* d_in, const int* in_sizes, int n_in,
                              void* d_out, int out_size)
{
    (void)in_sizes; (void)n_in; (void)out_size;
    const float* query = (const float*)d_in[0];
    const float* key   = (const float*)d_in[1];
    const float* value = (const float*)d_in[2];
    const float* mask  = (const float*)d_in[3];
    const unsigned char* kpm = (const unsigned char*)d_in[4];
    const float* Wq = (const float*)d_in[5];
    const float* bq = (const float*)d_in[6];
    const float* Wk = (const float*)d_in[7];
    const float* bk = (const float*)d_in[8];
    const float* Wv = (const float*)d_in[9];
    const float* bv = (const float*)d_in[10];
    const float* Wout = (const float*)d_in[11];
    const float* bout = (const float*)d_in[12];
    float* out = (float*)d_out;

    u16 *xh, *xl, *wh, *wl, *ph, *pl, *ah, *al;
    int* fp;
    cudaGetSymbolAddress((void**)&xh, g_xh);
    cudaGetSymbolAddress((void**)&xl, g_xl);
    cudaGetSymbolAddress((void**)&wh, g_wh);
    cudaGetSymbolAddress((void**)&wl, g_wl);
    cudaGetSymbolAddress((void**)&ph, g_ph);
    cudaGetSymbolAddress((void**)&pl, g_pl);
    cudaGetSymbolAddress((void**)&ah, g_ah);
    cudaGetSymbolAddress((void**)&al, g_al);
    cudaGetSymbolAddress((void**)&fp, g_flags);

    const size_t XN = (size_t)MT * CC;   // per input-split array
    const size_t WN = (size_t)CC * CC;
    const size_t PN = (size_t)BB * HH * TT * DD;

    cudaFuncSetAttribute(tc_gemm2<0>, cudaFuncAttributeMaxDynamicSharedMemorySize, GEMM_SMEM);
    cudaFuncSetAttribute(tc_gemm2<1>, cudaFuncAttributeMaxDynamicSharedMemorySize, GEMM_SMEM);
    cudaFuncSetAttribute(attn_tc2, cudaFuncAttributeMaxDynamicSharedMemorySize, ATTN_SMEM2);

    cudaMemsetAsync(fp, 0, sizeof(int));
    mask_check<<<1024, 256>>>(mask, kpm);

    // pre-split inputs + weights
    split_bf16<<<1024, 256>>>((const float4*)query, (uint4*)(xh + 0 * XN),
                              (uint4*)(xl + 0 * XN), (int)(XN / 8));
    split_bf16<<<1024, 256>>>((const float4*)key,   (uint4*)(xh + 1 * XN),
                              (uint4*)(xl + 1 * XN), (int)(XN / 8));
    split_bf16<<<1024, 256>>>((const float4*)value, (uint4*)(xh + 2 * XN),
                              (uint4*)(xl + 2 * XN), (int)(XN / 8));
    split_bf16<<<512, 256>>>((const float4*)Wq,   (uint4*)(wh + 0 * WN),
                             (uint4*)(wl + 0 * WN), (int)(WN / 8));
    split_bf16<<<512, 256>>>((const float4*)Wk,   (uint4*)(wh + 1 * WN),
                             (uint4*)(wl + 1 * WN), (int)(WN / 8));
    split_bf16<<<512, 256>>>((const float4*)Wv,   (uint4*)(wh + 2 * WN),
                             (uint4*)(wl + 2 * WN), (int)(WN / 8));
    split_bf16<<<512, 256>>>((const float4*)Wout, (uint4*)(wh + 3 * WN),
                             (uint4*)(wl + 3 * WN), (int)(WN / 8));

    dim3 ggrid(CC / 128, MT / 128);   // (8, 64)
    tc_gemm2<1><<<ggrid, 256, GEMM_SMEM>>>(xh + 0 * XN, xl + 0 * XN, wh + 0 * WN, wl + 0 * WN,
                                           bq, ph + 0 * PN, pl + 0 * PN, SCALE_F, MT, CC, CC);
    tc_gemm2<1><<<ggrid, 256, GEMM_SMEM>>>(xh + 1 * XN, xl + 1 * XN, wh + 1 * WN, wl + 1 * WN,
                                           bk, ph + 1 * PN, pl + 1 * PN, 1.0f, MT, CC, CC);
    tc_gemm2<1><<<ggrid, 256, GEMM_SMEM>>>(xh + 2 * XN, xl + 2 * XN, wh + 2 * WN, wl + 2 * WN,
                                           bv, ph + 2 * PN, pl + 2 * PN, 1.0f, MT, CC, CC);

    attn_tc2<<<dim3(TT / 128, HH, BB), 256, ATTN_SMEM2>>>(
        mask, kpm,
        ph + 0 * PN, pl + 0 * PN,
        ph + 1 * PN, pl + 1 * PN,
        ph + 2 * PN, pl + 2 * PN,
        ah, al);

    tc_gemm2<0><<<ggrid, 256, GEMM_SMEM>>>(ah, al, wh + 3 * WN, wl + 3 * WN,
                                           bout, out, nullptr, 1.0f, MT, CC, CC);
}